// round 7
// baseline (speedup 1.0000x reference)
#include <cuda_runtime.h>

#define AN 360
#define PN 512
#define IMGN 512
#define IMGSQ (IMGN*IMGN)
#define ROW 20            // floats per window row (16 batches + 4 pad)
#define WMAX 28
#define TPB 64
#define NG (AN/2)         // 180 groups of 2 angles

#define FMA2(acc, g, w) asm("fma.rn.f32x2 %0,%1,%2,%0;" : "+l"(acc) : "l"(g), "l"(w))
#define PACK2(d, s)     asm("mov.b64 %0,{%1,%1};" : "=l"(d) : "f"(s))

__global__ __launch_bounds__(TPB, 8)
void radon_bp(const float* __restrict__ sino,
              const float* __restrict__ thetas,
              const float* __restrict__ positions,
              float* __restrict__ out)
{
    __shared__ __align__(16) float4 s_acs[AN];                // {cos', sin', meta(bits), 0}
    __shared__ __align__(16) float  s_win[3][2][WMAX * ROW];  // triple buffer x 2 angles

    const int tid = threadIdx.x;
    // quad mapping: phase (8 lanes) = xq low 2 bits x yq low bit -> row spread <= 6.33, conflict-free
    const int xq = (tid & 3) | (((tid >> 5) & 1) << 2);   // 0..7 x-quad (pixels 2xq, 2xq+1)
    const int yq = ((tid >> 2) & 1) | (((tid >> 3) & 3) << 1); // 0..7 y-quad
    const int x0 = blockIdx.x * 16;
    const int y0 = blockIdx.y * 16;

    const float pos0   = positions[0];
    const float inv_dp = 1.0f / (positions[1] - pos0);
    const float pb     = -pos0 * inv_dp;

    const float half = (IMGN - 1) * 0.5f;
    const float cxm = (float)x0 - half, cxM = cxm + 15.0f;
    const float cym = (float)y0 - half, cyM = cym + 15.0f;

    // ---- init: trig + window meta: ((lo+128) & 0xFFFF) | (W<<16); 0 = skip ----
    for (int a = tid; a < AN; a += TPB) {
        float th = thetas[a];
        float c = cosf(th) * inv_dp;
        float s = sinf(th) * inv_dp;
        float t0 = c * cxm, t1 = c * cxM;
        float u0 = s * cym, u1 = s * cyM;
        float tmin = fminf(t0, t1) + fminf(u0, u1) + pb;
        float tmax = fmaxf(t0, t1) + fmaxf(u0, u1) + pb;
        int lo = __float2int_rd(tmin) - 1;          // UNclamped (may be <0 or >=PN)
        int W  = (__float2int_rd(tmax) + 3) - lo + 1;
        W = min(W, WMAX);
        int meta = 0;
        if (lo < PN && lo + W > 0)                  // window overlaps detector
            meta = ((lo + 128) & 0xFFFF) | (W << 16);
        s_acs[a] = make_float4(c, s, __int_as_float(meta), 0.0f);
    }

    const float fx = (float)(x0 + 2 * xq) - half;
    const float fy = (float)(y0 + 2 * yq) - half;

    unsigned long long acc[4][8];   // [px: (0,0),(1,0),(0,1),(1,1)][16 batches as f32x2]
    #pragma unroll
    for (int p = 0; p < 4; p++)
        #pragma unroll
        for (int q = 0; q < 8; q++) acc[p][q] = 0ull;

    // staging role: lane = window row, warp = batch octet
    const int sr   = tid & 31;
    const int hf   = tid >> 5;      // 0..1
    const size_t BSTR = (size_t)AN * PN;
    const float* sino_h = sino + (size_t)(8 * hf) * BSTR;
    const int sofs = sr * ROW + 8 * hf;

    __syncthreads();   // s_acs visible

    // stage one angle's window row (8 batches) into registers; returns store flag
    auto fetch = [&](int a, int meta, float* p) -> bool {
        if (!meta) return false;
        int lo = (meta & 0xFFFF) - 128;
        int W  = meta >> 16;
        if (sr >= W) return false;
        int rg  = lo + sr;
        bool inr = ((unsigned)rg < (unsigned)PN);
        int rc  = min(max(rg, 0), PN - 1);
        const float* b = sino_h + (size_t)a * PN + rc;
        #pragma unroll
        for (int i = 0; i < 8; i++) p[i] = __ldg(b + (size_t)i * BSTR);
        if (!inr) {
            #pragma unroll
            for (int i = 0; i < 8; i++) p[i] = 0.0f;
        }
        return true;
    };

    // ---- prologue: stage group 0 into buffer 0; prefetch group 1 ----
    {
        float p[8];
        #pragma unroll
        for (int ai = 0; ai < 2; ai++) {
            if (fetch(ai, __float_as_int(s_acs[ai].z), p)) {
                float* d = &s_win[0][ai][sofs];
                *(float4*)d       = make_float4(p[0], p[1], p[2], p[3]);
                *(float4*)(d + 4) = make_float4(p[4], p[5], p[6], p[7]);
            }
        }
    }
    float p0[8], p1[8];
    bool st0 = fetch(2, __float_as_int(s_acs[2].z), p0);
    bool st1 = fetch(3, __float_as_int(s_acs[3].z), p1);

    int buf_c = 0;

    #pragma unroll 1
    for (int g = 0; g < NG; g++) {
        const int a0 = 2 * g;
        const int buf_n = (buf_c == 2) ? 0 : buf_c + 1;

        // STS prefetched group g+1
        if (st0) {
            float* d = &s_win[buf_n][0][sofs];
            *(float4*)d       = make_float4(p0[0], p0[1], p0[2], p0[3]);
            *(float4*)(d + 4) = make_float4(p0[4], p0[5], p0[6], p0[7]);
        }
        if (st1) {
            float* d = &s_win[buf_n][1][sofs];
            *(float4*)d       = make_float4(p1[0], p1[1], p1[2], p1[3]);
            *(float4*)(d + 4) = make_float4(p1[4], p1[5], p1[6], p1[7]);
        }

        // LDG group g+2
        st0 = false; st1 = false;
        if (g + 2 < NG) {
            st0 = fetch(a0 + 4, __float_as_int(s_acs[a0 + 4].z), p0);
            st1 = fetch(a0 + 5, __float_as_int(s_acs[a0 + 5].z), p1);
        }

        __syncthreads();   // win[buf_c] (staged at iter g-1 top) visible

        #pragma unroll
        for (int ai = 0; ai < 2; ai++) {
            float4 acs = s_acs[a0 + ai];
            int m = __float_as_int(acs.z);
            if (!m) continue;
            const int lo = (m & 0xFFFF) - 128;
            const int W  = m >> 16;
            const float cp = acs.x, sp = acs.y;

            float f00 = fmaf(fx, cp, fmaf(fy, sp, pb));
            float fmn = f00 + fminf(cp, 0.0f) + fminf(sp, 0.0f);
            int jb = min(max(__float2int_rd(fmn) - lo, 0), W - 4);

            // d per pixel relative to window row jb
            float d0 = f00 - (float)(lo + jb);
            float d1 = d0 + cp;
            float d2 = d0 + sp;
            float d3 = d1 + sp;

            const float* win = &s_win[buf_c][ai][jb * ROW];

            #pragma unroll
            for (int r = 0; r < 4; r++) {
                const ulonglong2* rp = (const ulonglong2*)(win + r * ROW);
                ulonglong2 ga = rp[0], gb = rp[1], gc = rp[2], gd = rp[3];

                float fr = (float)r;
                float h0 = fmaxf(1.0f - fabsf(d0 - fr), 0.0f);
                float h1 = fmaxf(1.0f - fabsf(d1 - fr), 0.0f);
                float h2 = fmaxf(1.0f - fabsf(d2 - fr), 0.0f);
                float h3 = fmaxf(1.0f - fabsf(d3 - fr), 0.0f);
                unsigned long long W0, W1, W2, W3;
                PACK2(W0, h0); PACK2(W1, h1); PACK2(W2, h2); PACK2(W3, h3);

                FMA2(acc[0][0], ga.x, W0); FMA2(acc[0][1], ga.y, W0);
                FMA2(acc[0][2], gb.x, W0); FMA2(acc[0][3], gb.y, W0);
                FMA2(acc[0][4], gc.x, W0); FMA2(acc[0][5], gc.y, W0);
                FMA2(acc[0][6], gd.x, W0); FMA2(acc[0][7], gd.y, W0);

                FMA2(acc[1][0], ga.x, W1); FMA2(acc[1][1], ga.y, W1);
                FMA2(acc[1][2], gb.x, W1); FMA2(acc[1][3], gb.y, W1);
                FMA2(acc[1][4], gc.x, W1); FMA2(acc[1][5], gc.y, W1);
                FMA2(acc[1][6], gd.x, W1); FMA2(acc[1][7], gd.y, W1);

                FMA2(acc[2][0], ga.x, W2); FMA2(acc[2][1], ga.y, W2);
                FMA2(acc[2][2], gb.x, W2); FMA2(acc[2][3], gb.y, W2);
                FMA2(acc[2][4], gc.x, W2); FMA2(acc[2][5], gc.y, W2);
                FMA2(acc[2][6], gd.x, W2); FMA2(acc[2][7], gd.y, W2);

                FMA2(acc[3][0], ga.x, W3); FMA2(acc[3][1], ga.y, W3);
                FMA2(acc[3][2], gb.x, W3); FMA2(acc[3][3], gb.y, W3);
                FMA2(acc[3][4], gc.x, W3); FMA2(acc[3][5], gc.y, W3);
                FMA2(acc[3][6], gd.x, W3); FMA2(acc[3][7], gd.y, W3);
            }
        }

        buf_c = buf_n;
    }

    // ---- epilogue: out[b, 0, y, x] ----
    const int xb = x0 + 2 * xq;
    const int yb = y0 + 2 * yq;
    float* ob = out + (size_t)yb * IMGN + xb;
    #pragma unroll
    for (int q = 0; q < 8; q++) {
        float2 a0 = *(float2*)&acc[0][q];
        float2 a1 = *(float2*)&acc[1][q];
        float2 a2 = *(float2*)&acc[2][q];
        float2 a3 = *(float2*)&acc[3][q];
        size_t b0 = (size_t)(2 * q) * IMGSQ;
        size_t b1 = b0 + IMGSQ;
        *(float2*)(ob + b0)         = make_float2(a0.x, a1.x);
        *(float2*)(ob + b0 + IMGN)  = make_float2(a2.x, a3.x);
        *(float2*)(ob + b1)         = make_float2(a0.y, a1.y);
        *(float2*)(ob + b1 + IMGN)  = make_float2(a2.y, a3.y);
    }
}

extern "C" void kernel_launch(void* const* d_in, const int* in_sizes, int n_in,
                              void* d_out, int out_size)
{
    const float* sino      = (const float*)d_in[0];
    const float* thetas    = (const float*)d_in[1];
    const float* positions = (const float*)d_in[2];
    float* out             = (float*)d_out;

    dim3 grid(IMGN / 16, IMGN / 16);   // 32 x 32 = 1024 tiles
    radon_bp<<<grid, TPB>>>(sino, thetas, positions, out);
}